// round 6
// baseline (speedup 1.0000x reference)
#include <cuda_runtime.h>

// Skip-gram negative-sampling loss.
// Inputs (metadata order): pos_u [B] i32, pos_v [B] i32, neg_v [B,10] i32,
//                          u_weight [V,128] f32, v_weight [V,128] f32
// Output: scalar f32 = mean_b( softplus(-clip(u.v)) - sum_n softplus(u.neg_n) )

#define DIM   128
#define NNEG  10
#define MAX_PARTIALS 16384

__device__ float g_partials[MAX_PARTIALS];

__device__ __forceinline__ float softplusf(float x) {
    // log(1 + e^x), numerically stable
    return x > 0.0f ? x + log1pf(__expf(-x)) : log1pf(__expf(x));
}

__global__ void __launch_bounds__(256)
skipgram_kernel(const int* __restrict__ pos_u,
                const int* __restrict__ pos_v,
                const int* __restrict__ neg_v,
                const float4* __restrict__ uw,   // [V, 32] float4
                const float4* __restrict__ vw,   // [V, 32] float4
                int batch)
{
    const int lane = threadIdx.x & 31;
    const int warp = threadIdx.x >> 5;
    const int b = blockIdx.x * (blockDim.x >> 5) + warp;

    __shared__ float s_warp[8];

    float loss = 0.0f;
    if (b < batch) {
        const int iu = __ldg(pos_u + b);
        const int iv = __ldg(pos_v + b);

        // Each lane owns 4 consecutive floats of the 128-dim row.
        const float4 u = uw[(size_t)iu * 32 + lane];
        const float4 v = vw[(size_t)iv * 32 + lane];

        float acc[NNEG + 1];
        acc[0] = u.x * v.x + u.y * v.y + u.z * v.z + u.w * v.w;

        #pragma unroll
        for (int n = 0; n < NNEG; n++) {
            const int in_ = __ldg(neg_v + (size_t)b * NNEG + n);
            const float4 w = vw[(size_t)in_ * 32 + lane];
            acc[n + 1] = u.x * w.x + u.y * w.y + u.z * w.z + u.w * w.w;
        }

        // Butterfly-reduce all 11 dots; independent accumulators pipeline the shuffles.
        #pragma unroll
        for (int n = 0; n < NNEG + 1; n++) {
            float a = acc[n];
            a += __shfl_xor_sync(0xffffffffu, a, 16);
            a += __shfl_xor_sync(0xffffffffu, a, 8);
            a += __shfl_xor_sync(0xffffffffu, a, 4);
            a += __shfl_xor_sync(0xffffffffu, a, 2);
            a += __shfl_xor_sync(0xffffffffu, a, 1);
            acc[n] = a;
        }

        const float sc = fminf(fmaxf(acc[0], -10.0f), 10.0f);
        loss = softplusf(-sc);                 // -log_sigmoid(score)
        #pragma unroll
        for (int n = 1; n <= NNEG; n++)
            loss -= softplusf(acc[n]);         // + log_sigmoid(-neg_dot)
    }

    // Block reduction (deterministic: fixed order).
    if (lane == 0) s_warp[warp] = loss;
    __syncthreads();
    if (threadIdx.x == 0) {
        float p = 0.0f;
        const int nw = blockDim.x >> 5;
        #pragma unroll
        for (int i = 0; i < 8; i++)
            if (i < nw) p += s_warp[i];
        g_partials[blockIdx.x] = p;
    }
}

__global__ void __launch_bounds__(1024)
reduce_kernel(float* __restrict__ out, int nparts, float inv_batch)
{
    __shared__ float s[1024];
    float p = 0.0f;
    for (int i = threadIdx.x; i < nparts; i += 1024)
        p += g_partials[i];
    s[threadIdx.x] = p;
    __syncthreads();
    #pragma unroll
    for (int off = 512; off > 0; off >>= 1) {
        if (threadIdx.x < off) s[threadIdx.x] += s[threadIdx.x + off];
        __syncthreads();
    }
    if (threadIdx.x == 0) *out = s[0] * inv_batch;
}

extern "C" void kernel_launch(void* const* d_in, const int* in_sizes, int n_in,
                              void* d_out, int out_size)
{
    const int*    pos_u = (const int*)d_in[0];
    const int*    pos_v = (const int*)d_in[1];
    const int*    neg_v = (const int*)d_in[2];
    const float4* uw    = (const float4*)d_in[3];
    const float4* vw    = (const float4*)d_in[4];

    const int batch = in_sizes[0];
    const int threads = 256;
    const int wpb = threads / 32;
    const int blocks = (batch + wpb - 1) / wpb;   // 8192 for B=65536

    skipgram_kernel<<<blocks, threads>>>(pos_u, pos_v, neg_v, uw, vw, batch);
    reduce_kernel<<<1, 1024>>>((float*)d_out, blocks, 1.0f / (float)batch);
}